// round 5
// baseline (speedup 1.0000x reference)
#include <cuda_runtime.h>
#include <cuda_bf16.h>

// Segment-sum over sorted segment_ids.
// feat: [N_ROWS, 128] f32, segment_ids: [N_ROWS] i32 (sorted, non-decreasing),
// out: [N_SEGMENTS, 128] f32.
//
// Strategy: one warp per 128-row chunk. Each lane accumulates 4 columns
// (float4). Sortedness => if seg[r+7] == cur then all of rows r..r+7 belong
// to segment cur (monotone), so the hot loop is 1 id load + 8 independent
// float4 loads per 8 rows. Boundary rows handled scalarly; flushes use
// atomicAdd (rare: ~1 flush per chunk + ~1 per segment boundary).

#define D_FEAT 128
#define LANES_F4 (D_FEAT / 4)      // 32 float4 per row == 32 lanes
#define ROWS_PER_WARP 128
#define THREADS_PER_BLOCK 256
#define WARPS_PER_BLOCK (THREADS_PER_BLOCK / 32)

__global__ void zero_out_kernel(float4* __restrict__ out, int n4) {
    int i = blockIdx.x * blockDim.x + threadIdx.x;
    if (i < n4) out[i] = make_float4(0.f, 0.f, 0.f, 0.f);
}

__device__ __forceinline__ void flush_acc(float* __restrict__ out, int seg,
                                          int lane, float4& acc) {
    if (acc.x != 0.f || acc.y != 0.f || acc.z != 0.f || acc.w != 0.f || true) {
        float* dst = out + (size_t)seg * D_FEAT + lane * 4;
        atomicAdd(dst + 0, acc.x);
        atomicAdd(dst + 1, acc.y);
        atomicAdd(dst + 2, acc.z);
        atomicAdd(dst + 3, acc.w);
    }
    acc = make_float4(0.f, 0.f, 0.f, 0.f);
}

__global__ __launch_bounds__(THREADS_PER_BLOCK)
void segment_sum_kernel(const float4* __restrict__ feat4,
                        const int* __restrict__ seg,
                        float* __restrict__ out,
                        int n_rows) {
    const int warp_global = (blockIdx.x * WARPS_PER_BLOCK) + (threadIdx.x >> 5);
    const int lane = threadIdx.x & 31;

    int row0 = warp_global * ROWS_PER_WARP;
    if (row0 >= n_rows) return;
    int row_end = row0 + ROWS_PER_WARP;
    if (row_end > n_rows) row_end = n_rows;

    float4 acc = make_float4(0.f, 0.f, 0.f, 0.f);
    int cur = __ldg(seg + row0);

    int r = row0;
    while (r < row_end) {
        if (r + 8 <= row_end && __ldg(seg + r + 7) == cur) {
            // Fast path: all 8 rows in segment `cur`. 8 independent loads.
            const float4* p = feat4 + (size_t)r * LANES_F4 + lane;
            float4 v0 = __ldg(p + 0 * LANES_F4);
            float4 v1 = __ldg(p + 1 * LANES_F4);
            float4 v2 = __ldg(p + 2 * LANES_F4);
            float4 v3 = __ldg(p + 3 * LANES_F4);
            float4 v4 = __ldg(p + 4 * LANES_F4);
            float4 v5 = __ldg(p + 5 * LANES_F4);
            float4 v6 = __ldg(p + 6 * LANES_F4);
            float4 v7 = __ldg(p + 7 * LANES_F4);
            // pairwise tree to shorten the dependent-add chain
            float4 s01, s23, s45, s67, s03, s47;
            s01.x = v0.x + v1.x; s01.y = v0.y + v1.y; s01.z = v0.z + v1.z; s01.w = v0.w + v1.w;
            s23.x = v2.x + v3.x; s23.y = v2.y + v3.y; s23.z = v2.z + v3.z; s23.w = v2.w + v3.w;
            s45.x = v4.x + v5.x; s45.y = v4.y + v5.y; s45.z = v4.z + v5.z; s45.w = v4.w + v5.w;
            s67.x = v6.x + v7.x; s67.y = v6.y + v7.y; s67.z = v6.z + v7.z; s67.w = v6.w + v7.w;
            s03.x = s01.x + s23.x; s03.y = s01.y + s23.y; s03.z = s01.z + s23.z; s03.w = s01.w + s23.w;
            s47.x = s45.x + s67.x; s47.y = s45.y + s67.y; s47.z = s45.z + s67.z; s47.w = s45.w + s67.w;
            acc.x += s03.x + s47.x;
            acc.y += s03.y + s47.y;
            acc.z += s03.z + s47.z;
            acc.w += s03.w + s47.w;
            r += 8;
        } else {
            // Slow path: segment boundary within the next 8 rows (or tail).
            int sid = __ldg(seg + r);
            if (sid != cur) {
                flush_acc(out, cur, lane, acc);
                cur = sid;
            }
            float4 v = __ldg(feat4 + (size_t)r * LANES_F4 + lane);
            acc.x += v.x; acc.y += v.y; acc.z += v.z; acc.w += v.w;
            r += 1;
        }
    }
    flush_acc(out, cur, lane, acc);
}

extern "C" void kernel_launch(void* const* d_in, const int* in_sizes, int n_in,
                              void* d_out, int out_size) {
    const float* feat = (const float*)d_in[0];
    const int* seg = (const int*)d_in[1];
    float* out = (float*)d_out;

    const int n_rows = in_sizes[1];            // segment_ids element count
    // sanity: in_sizes[0] == n_rows * D_FEAT

    // 1) zero the (poisoned) output
    int n4 = out_size / 4;
    zero_out_kernel<<<(n4 + THREADS_PER_BLOCK - 1) / THREADS_PER_BLOCK,
                      THREADS_PER_BLOCK>>>((float4*)out, n4);

    // 2) segment sum
    int total_warps = (n_rows + ROWS_PER_WARP - 1) / ROWS_PER_WARP;
    int blocks = (total_warps + WARPS_PER_BLOCK - 1) / WARPS_PER_BLOCK;
    segment_sum_kernel<<<blocks, THREADS_PER_BLOCK>>>(
        (const float4*)feat, seg, out, n_rows);
}